// round 14
// baseline (speedup 1.0000x reference)
#include <cuda_runtime.h>

// SSIM loss, fully fused one-kernel version, 4-plane formulation with the
// vertical accumulator ring packed as f32x2 (planes x|y and x2+y2|xy).
// img1, img2: [32,3,512,512] fp32. Output: scalar fp32 = 1 - mean(ssim_map).
//
// Rationale: issue-slot bound kernel (issue 62.5%, fma pipe only 46.8%).
// FFMA2 halves vertical issue count at identical fma-pipe cycles and
// IDENTICAL register inventory (packed accs = same 44 regs as scalar ring).
// Staging layout, HSTEP (scalar, conflict-free LDS.128), barriers, and the
// fused reduction are byte-identical to the proven 150.2us R13 kernel.

#define HW       512
#define NPLANES  96
#define BAND     44
#define NBANDS   12
#define NBLK     (NBANDS * NPLANES)   // 1152
#define VB       528
#define VB4      (VB / 4)
#define SMEM_DYN (2 * 4 * 4 * VB4 * 16)   // 67584 bytes

typedef unsigned long long ull;

namespace {
constexpr double G_[6] = {0.0038659201595884, 0.0285655007845504,
                          0.1353352832366127, 0.4111122905071874,
                          0.8007374029168081, 1.0};
constexpr double GSUM = 2.0*(G_[0]+G_[1]+G_[2]+G_[3]+G_[4]) + 1.0;
constexpr float gwf(int j){ return (float)(G_[j < 6 ? j : 10 - j] / GSUM); }
}

__device__ constexpr float GW[11] = {
    gwf(0), gwf(1), gwf(2), gwf(3), gwf(4), gwf(5),
    gwf(6), gwf(7), gwf(8), gwf(9), gwf(10)};

__device__ float    g_part[NBLK];
__device__ unsigned g_count = 0;

__device__ __forceinline__ ull pack2(float a, float b) {
    ull r; asm("mov.b64 %0, {%1, %2};" : "=l"(r) : "f"(a), "f"(b)); return r;
}
__device__ __forceinline__ void unpack2(float& a, float& b, ull v) {
    asm("mov.b64 {%0, %1}, %2;" : "=f"(a), "=f"(b) : "l"(v));
}
__device__ __forceinline__ ull fma2(ull a, ull b, ull c) {
    ull d; asm("fma.rn.f32x2 %0, %1, %2, %3;" : "=l"(d) : "l"(a), "l"(b), "l"(c));
    return d;
}
__device__ __forceinline__ ull mul2(ull a, ull b) {
    ull d; asm("mul.rn.f32x2 %0, %1, %2;" : "=l"(d) : "l"(a), "l"(b)); return d;
}

// Packed ingest: deposit j of ingested row (ring phase PH) -> slot
// (PH+j+6)%11, belonging to output row o = r + j - 5. JMIN masks prologue
// deposits (only o >= o0). j == 10 is always the FIRST write to its slot
// since that slot's emit (validated R6/R7) -> MUL2, no ring init anywhere.
// A01 lanes = (x, y); A23 lanes = (x^2+y^2, x*y).
template<int PH, int JMIN>
__device__ __forceinline__ void ingest2(ull (&A01)[11], ull (&A23)[11],
                                        const ull (&WP)[6], float v1, float v2)
{
    const ull P01 = pack2(v1, v2);
    const ull SQ  = mul2(P01, P01);       // (x^2, y^2)
    float xs, ys; unpack2(xs, ys, SQ);
    const float q23 = xs + ys;            // x^2 + y^2
    const float q4  = v1 * v2;            // x*y
    const ull P23 = pack2(q23, q4);
#pragma unroll
    for (int j = JMIN; j < 11; ++j) {
        const int s  = (PH + j + 6) % 11;
        const int wi = j < 6 ? j : 10 - j;
        if (j == 10) {
            A01[s] = mul2(WP[wi], P01);
            A23[s] = mul2(WP[wi], P23);
        } else {
            A01[s] = fma2(WP[wi], P01, A01[s]);
            A23[s] = fma2(WP[wi], P23, A23[s]);
        }
    }
}

__global__ __launch_bounds__(512, 1)
void ssim_main(const float* __restrict__ img1, const float* __restrict__ img2,
               float* __restrict__ out)
{
    extern __shared__ float4 dynbuf[];   // [2][4][4][VB4], scalar SoA staging
#define VBUF(B, P, S) ((float*)(dynbuf + (((B)*4 + (P))*4 + (S)) * VB4))

    const int c     = threadIdx.x;
    const int band  = blockIdx.x;
    const int plane = blockIdx.y;
    const int o0    = band * BAND;
    const float* __restrict__ p1 = img1 + (size_t)plane * HW * HW;
    const float* __restrict__ p2 = img2 + (size_t)plane * HW * HW;

    __shared__ float  red[16];
    __shared__ double sd[512];
    __shared__ int    amLast;

    // packed weights (6 distinct, symmetric kernel) — register resident
    ull WP[6];
#pragma unroll
    for (int k = 0; k < 6; ++k) WP[k] = pack2(GW[k], GW[k]);

    // one-time zero of column borders (emits only touch [5,516])
#pragma unroll
    for (int b = 0; b < 2; ++b)
#pragma unroll
        for (int p = 0; p < 4; ++p)
#pragma unroll
            for (int s = 0; s < 4; ++s) {
                float* bb = VBUF(b, p, s);
                if (c < 5)    bb[c] = 0.f;
                if (c >= 501) bb[c + 16] = 0.f;   // 517..527
            }

    ull a01[11], a23[11];   // no init: first touch of every slot is MUL2

    __syncthreads();

    // single prefetch bank: group G's ingest rows, loaded at top of GBODY(G)
    // (consumed after HSTEP, ~400+ cyc downstream). Saves 8 regs vs 2 banks.
    float nv1[4], nv2[4];
#define LOADS(G) {                                                           \
        _Pragma("unroll")                                                    \
        for (int i = 0; i < 4; ++i) {                                        \
            const int  r_  = o0 + 4 * (G) + 5 + i;                           \
            const bool ok_ = r_ < HW;                                        \
            nv1[i] = ok_ ? __ldg(&p1[(size_t)r_ * HW + c]) : 0.f;            \
            nv2[i] = ok_ ? __ldg(&p2[(size_t)r_ * HW + c]) : 0.f;            \
        } }

    // group-0 ingest loads first; the prologue FMA chain hides their latency
    LOADS(0)

    // ── prologue: rows o0-5 .. o0+4, JMIN = 10-i masking ──
#define PROLOG(i) {                                                          \
        const int  r_  = o0 - 5 + (i);                                       \
        const bool ok_ = (unsigned)r_ < (unsigned)HW;                        \
        const float v1_ = ok_ ? __ldg(&p1[(size_t)r_ * HW + c]) : 0.f;       \
        const float v2_ = ok_ ? __ldg(&p2[(size_t)r_ * HW + c]) : 0.f;       \
        ingest2<((i) + 6) % 11, 10 - (i)>(a01, a23, WP, v1_, v2_); }
    PROLOG(0) PROLOG(1) PROLOG(2) PROLOG(3) PROLOG(4)
    PROLOG(5) PROLOG(6) PROLOG(7) PROLOG(8) PROLOG(9)
#undef PROLOG

    // ingest + emit sub-row i of group G: row o0+4G+5+i, slot (4G+i)%11;
    // unpack the packed slots into the SAME scalar SoA staging as R13.
#define ING(G, i) {                                                          \
        ingest2<((4 * (G) + (i)) + 5) % 11, 0>(a01, a23, WP,                 \
                                               nv1[(i)], nv2[(i)]);          \
        const int sl_ = (4 * (G) + (i)) % 11;                                \
        float e0_, e1_, e2_, e3_;                                            \
        unpack2(e0_, e1_, a01[sl_]);                                         \
        unpack2(e2_, e3_, a23[sl_]);                                         \
        VBUF((G) & 1, 0, (i))[c + 5] = e0_;                                  \
        VBUF((G) & 1, 1, (i))[c + 5] = e1_;                                  \
        VBUF((G) & 1, 2, (i))[c + 5] = e2_;                                  \
        VBUF((G) & 1, 3, (i))[c + 5] = e3_; }

    float lsum = 0.f;
    const int rr = c >> 7;            // horizontal: row within group
    const int cq = c & 127;           // horizontal: float4 index

    // horizontal conv + SSIM for group G out of buffer B (R13 exact shape)
#define HSTEP(G, B) {                                                        \
        float hr[4][4];                                                      \
        _Pragma("unroll")                                                    \
        for (int p = 0; p < 4; ++p) {                                        \
            const float4* q = dynbuf + (((B)*4 + p)*4 + rr) * VB4 + cq;      \
            const float4 A = q[0], Bv = q[1], Cv = q[2], D = q[3];           \
            const float v[16] = {A.x, A.y, A.z, A.w,  Bv.x, Bv.y, Bv.z, Bv.w,\
                                 Cv.x, Cv.y, Cv.z, Cv.w,  D.x, D.y, D.z, D.w};\
            _Pragma("unroll")                                                \
            for (int i = 0; i < 4; ++i) {                                    \
                float s = GW[0] * v[i];                                      \
                _Pragma("unroll")                                            \
                for (int k = 1; k < 11; ++k) s = fmaf(GW[k], v[i + k], s);   \
                hr[p][i] = s;                                                \
            }                                                                \
        }                                                                    \
        const int o = o0 + 4 * (G) + rr;                                     \
        if (o < HW) {                                                        \
            _Pragma("unroll")                                                \
            for (int i = 0; i < 4; ++i) {                                    \
                const float C1 = 1e-4f, C2 = 9e-4f;                          \
                const float m1 = hr[0][i], m2 = hr[1][i];                    \
                const float mu12 = m1 * m2;                                  \
                const float msum = fmaf(m1, m1, m2 * m2);                    \
                const float Anum = 2.f * mu12 + C1;                          \
                const float Bnum = 2.f * (hr[3][i] - mu12) + C2;             \
                const float Cden = msum + C1;                                \
                const float Dden = (hr[2][i] - msum) + C2;                   \
                lsum += __fdividef(Anum * Bnum, Cden * Dden);                \
            }                                                                \
        } }

    // group 0: bank already loaded, ingest + emit buf 0
    ING(0, 0) ING(0, 1) ING(0, 2) ING(0, 3)

#define GBODY(G) {                                                           \
        __syncthreads();                                                     \
        LOADS(G)                                                             \
        HSTEP((G) - 1, ((G) - 1) & 1)                                        \
        ING(G, 0) ING(G, 1) ING(G, 2) ING(G, 3) }
    GBODY(1) GBODY(2) GBODY(3) GBODY(4) GBODY(5)
    GBODY(6) GBODY(7) GBODY(8) GBODY(9) GBODY(10)
#undef GBODY

    __syncthreads();
    HSTEP(10, 0)

#undef HSTEP
#undef ING
#undef LOADS
#undef VBUF

    // ── block reduction ──
    float v = lsum;
#pragma unroll
    for (int off = 16; off; off >>= 1)
        v += __shfl_xor_sync(0xFFFFFFFFu, v, off);
    if ((c & 31) == 0) red[c >> 5] = v;
    __syncthreads();

    if (c == 0) {
        float bs = 0.f;
#pragma unroll
        for (int w = 0; w < 16; ++w) bs += red[w];
        g_part[plane * NBANDS + band] = bs;
        __threadfence();
        const unsigned t = atomicAdd(&g_count, 1u);
        amLast = (t == NBLK - 1);
    }
    __syncthreads();

    if (amLast) {
        __threadfence();
        double s = 0.0;
        for (int i = c; i < NBLK; i += 512) s += (double)g_part[i];
        sd[c] = s;
        __syncthreads();
#pragma unroll
        for (int k = 256; k > 0; k >>= 1) {
            if (c < k) sd[c] += sd[c + k];
            __syncthreads();
        }
        if (c == 0) {
            out[0]  = (float)(1.0 - sd[0] / 25165824.0);  // 32*3*512*512
            g_count = 0;                                   // reset for replay
        }
    }
}

extern "C" void kernel_launch(void* const* d_in, const int* in_sizes, int n_in,
                              void* d_out, int out_size)
{
    (void)in_sizes; (void)n_in; (void)out_size;
    const float* img1 = (const float*)d_in[0];
    const float* img2 = (const float*)d_in[1];
    cudaFuncSetAttribute(ssim_main, cudaFuncAttributeMaxDynamicSharedMemorySize,
                         SMEM_DYN);
    dim3 grid(NBANDS, NPLANES);
    ssim_main<<<grid, 512, SMEM_DYN>>>(img1, img2, (float*)d_out);
}